// round 3
// baseline (speedup 1.0000x reference)
#include <cuda_runtime.h>

// Problem constants
#define B_   4
#define T_   2048
#define E_   1024
#define H_   16
#define DH_  64
#define M_   (B_ * T_)     // 8192 rows
#define NQKV (3 * E_)      // 3072

// Scratch (allocation-free rule: __device__ globals)
__device__ float g_qkv[(size_t)M_ * NQKV];  // 96 MB: [M, 3E]  (Q | K | V per row)
__device__ float g_att[(size_t)M_ * E_];    // 32 MB: attention output [M, E]

// ---------------------------------------------------------------------------
// NT SGEMM with bias: C[M,N] = A[M,K] @ B[N,K]^T + bias[N]
// 128x128 block tile, BK=8, 256 threads, 8x8 per-thread micro-tile split as
// 2x(4 rows)+2x(4 cols) at +64 offsets to minimize smem read conflicts.
// M,N,K assumed multiples of 128/128/8 (true for all calls here).
// ---------------------------------------------------------------------------
__global__ __launch_bounds__(256) void sgemm_nt_bias(
    const float* __restrict__ A, const float* __restrict__ Bm,
    const float* __restrict__ bias, float* __restrict__ C,
    int M, int N, int K)
{
    __shared__ float As[8][128];
    __shared__ float Bs[8][128];

    const int tid  = threadIdx.x;
    const int m0   = blockIdx.y * 128;
    const int n0   = blockIdx.x * 128;
    const int lrow = tid >> 1;           // 0..127
    const int lcol = (tid & 1) << 2;     // 0 or 4
    const int tx   = tid & 15;
    const int ty   = tid >> 4;

    const float* Ap = A  + (size_t)(m0 + lrow) * K + lcol;
    const float* Bp = Bm + (size_t)(n0 + lrow) * K + lcol;

    float acc[8][8];
    #pragma unroll
    for (int i = 0; i < 8; ++i)
        #pragma unroll
        for (int j = 0; j < 8; ++j) acc[i][j] = 0.f;

    for (int k0 = 0; k0 < K; k0 += 8) {
        float4 av = *(const float4*)(Ap + k0);
        float4 bv = *(const float4*)(Bp + k0);
        As[lcol + 0][lrow] = av.x; As[lcol + 1][lrow] = av.y;
        As[lcol + 2][lrow] = av.z; As[lcol + 3][lrow] = av.w;
        Bs[lcol + 0][lrow] = bv.x; Bs[lcol + 1][lrow] = bv.y;
        Bs[lcol + 2][lrow] = bv.z; Bs[lcol + 3][lrow] = bv.w;
        __syncthreads();

        #pragma unroll
        for (int k = 0; k < 8; ++k) {
            float a[8], b[8];
            float4 t0 = *(const float4*)&As[k][ty * 4];
            float4 t1 = *(const float4*)&As[k][ty * 4 + 64];
            a[0] = t0.x; a[1] = t0.y; a[2] = t0.z; a[3] = t0.w;
            a[4] = t1.x; a[5] = t1.y; a[6] = t1.z; a[7] = t1.w;
            float4 u0 = *(const float4*)&Bs[k][tx * 4];
            float4 u1 = *(const float4*)&Bs[k][tx * 4 + 64];
            b[0] = u0.x; b[1] = u0.y; b[2] = u0.z; b[3] = u0.w;
            b[4] = u1.x; b[5] = u1.y; b[6] = u1.z; b[7] = u1.w;
            #pragma unroll
            for (int i = 0; i < 8; ++i)
                #pragma unroll
                for (int j = 0; j < 8; ++j)
                    acc[i][j] += a[i] * b[j];
        }
        __syncthreads();
    }

    // Epilogue: rows m0 + ih*64 + ty*4 + i, cols n0 + jh*64 + tx*4 + j
    #pragma unroll
    for (int ih = 0; ih < 2; ++ih) {
        #pragma unroll
        for (int i = 0; i < 4; ++i) {
            const int row = m0 + ih * 64 + ty * 4 + i;
            #pragma unroll
            for (int jh = 0; jh < 2; ++jh) {
                const int col = n0 + jh * 64 + tx * 4;
                float4 o;
                o.x = acc[ih * 4 + i][jh * 4 + 0] + bias[col + 0];
                o.y = acc[ih * 4 + i][jh * 4 + 1] + bias[col + 1];
                o.z = acc[ih * 4 + i][jh * 4 + 2] + bias[col + 2];
                o.w = acc[ih * 4 + i][jh * 4 + 3] + bias[col + 3];
                *(float4*)(C + (size_t)row * N + col) = o;
            }
        }
    }
}

// ---------------------------------------------------------------------------
// Flash attention (fp32, causal). One block = 64 query rows of one (b,h).
// 256 threads: ty=tid/16 picks 4 query rows (r0=4*ty), tx=tid%16 picks 4 cols
// (c0=4*tx) — the same mapping serves the S tile (cols = keys) and the O tile
// (cols = head dims). Online softmax with per-row stats replicated across the
// 16 lanes of a row group (reduced with xor-shuffles within the low 4 lane
// bits, which never cross the ty boundary at bit 4).
// ---------------------------------------------------------------------------
#define FL_LDP 65                         // padded row stride (floats)
#define FL_SMEM (4 * 64 * FL_LDP * sizeof(float))   // Qs,Ks,Ps,Vs = 66560 B

__global__ __launch_bounds__(256) void flash_attn(
    const float* __restrict__ qkv, float* __restrict__ att)
{
    extern __shared__ float sm[];
    float* Qs = sm;
    float* Ks = sm + 1 * 64 * FL_LDP;
    float* Ps = sm + 2 * 64 * FL_LDP;
    float* Vs = sm + 3 * 64 * FL_LDP;

    const int tid = threadIdx.x;
    const int tx  = tid & 15;
    const int ty  = tid >> 4;
    const int r0  = ty * 4;
    const int c0  = tx * 4;
    const int q0  = blockIdx.x * 64;
    const int b   = blockIdx.y >> 4;
    const int h   = blockIdx.y & 15;

    const float* qb = qkv + (size_t)b * T_ * NQKV + h * DH_;
    const float* kb = qb + E_;
    const float* vb = qb + 2 * E_;

    // cooperative tile-load indexing: 4 threads per row, 16 floats each
    const int lr = tid >> 2;         // 0..63
    const int lc = (tid & 3) * 16;   // 0,16,32,48

    { // load Q tile once
        const float* src = qb + (size_t)(q0 + lr) * NQKV + lc;
        #pragma unroll
        for (int u = 0; u < 4; ++u) {
            float4 v = *(const float4*)(src + u * 4);
            float* d = Qs + lr * FL_LDP + lc + u * 4;
            d[0] = v.x; d[1] = v.y; d[2] = v.z; d[3] = v.w;
        }
    }

    float m[4], l[4], acc[4][4];
    #pragma unroll
    for (int i = 0; i < 4; ++i) {
        m[i] = -1e30f; l[i] = 0.f;
        #pragma unroll
        for (int j = 0; j < 4; ++j) acc[i][j] = 0.f;
    }

    for (int j0 = 0; j0 <= q0; j0 += 64) {
        __syncthreads();   // prev tile's P·V done reading Ps/Vs
        { // load K/V tiles
            const float* ksrc = kb + (size_t)(j0 + lr) * NQKV + lc;
            const float* vsrc = vb + (size_t)(j0 + lr) * NQKV + lc;
            #pragma unroll
            for (int u = 0; u < 4; ++u) {
                float4 kv4 = *(const float4*)(ksrc + u * 4);
                float4 vv4 = *(const float4*)(vsrc + u * 4);
                float* dk = Ks + lr * FL_LDP + lc + u * 4;
                float* dv = Vs + lr * FL_LDP + lc + u * 4;
                dk[0] = kv4.x; dk[1] = kv4.y; dk[2] = kv4.z; dk[3] = kv4.w;
                dv[0] = vv4.x; dv[1] = vv4.y; dv[2] = vv4.z; dv[3] = vv4.w;
            }
        }
        __syncthreads();

        // S = Q K^T (4x4 micro-tile, dot over 64)
        float s[4][4];
        #pragma unroll
        for (int i = 0; i < 4; ++i)
            #pragma unroll
            for (int j = 0; j < 4; ++j) s[i][j] = 0.f;

        #pragma unroll 8
        for (int k = 0; k < 64; ++k) {
            float qv[4], kv[4];
            #pragma unroll
            for (int i = 0; i < 4; ++i) qv[i] = Qs[(r0 + i) * FL_LDP + k];
            #pragma unroll
            for (int j = 0; j < 4; ++j) kv[j] = Ks[(c0 + j) * FL_LDP + k];
            #pragma unroll
            for (int i = 0; i < 4; ++i)
                #pragma unroll
                for (int j = 0; j < 4; ++j)
                    s[i][j] += qv[i] * kv[j];
        }

        const bool diag = (j0 == q0);
        #pragma unroll
        for (int i = 0; i < 4; ++i) {
            const int gr = q0 + r0 + i;
            float mx = -1e30f;
            #pragma unroll
            for (int j = 0; j < 4; ++j) {
                float sv = s[i][j] * 0.125f;   // SCALE = DH^-0.5 = 1/8 exactly
                if (diag && (j0 + c0 + j > gr)) sv = -1e30f;
                s[i][j] = sv;
                mx = fmaxf(mx, sv);
            }
            #pragma unroll
            for (int d = 8; d > 0; d >>= 1)
                mx = fmaxf(mx, __shfl_xor_sync(0xffffffffu, mx, d));
            const float mnew  = fmaxf(m[i], mx);
            const float alpha = __expf(m[i] - mnew);
            float rs = 0.f;
            #pragma unroll
            for (int j = 0; j < 4; ++j) {
                float p = __expf(s[i][j] - mnew);
                Ps[(r0 + i) * FL_LDP + c0 + j] = p;
                rs += p;
            }
            #pragma unroll
            for (int d = 8; d > 0; d >>= 1)
                rs += __shfl_xor_sync(0xffffffffu, rs, d);
            l[i] = l[i] * alpha + rs;
            m[i] = mnew;
            #pragma unroll
            for (int j = 0; j < 4; ++j) acc[i][j] *= alpha;
        }
        __syncthreads();   // Ps complete

        // O += P V (4 rows x 4 head-dims, sum over 64 keys)
        #pragma unroll 8
        for (int j = 0; j < 64; ++j) {
            float pv[4], vv[4];
            #pragma unroll
            for (int i = 0; i < 4; ++i) pv[i] = Ps[(r0 + i) * FL_LDP + j];
            #pragma unroll
            for (int d = 0; d < 4; ++d) vv[d] = Vs[j * FL_LDP + c0 + d];
            #pragma unroll
            for (int i = 0; i < 4; ++i)
                #pragma unroll
                for (int d = 0; d < 4; ++d)
                    acc[i][d] += pv[i] * vv[d];
        }
    }

    #pragma unroll
    for (int i = 0; i < 4; ++i) {
        const float inv = 1.0f / l[i];
        float* dst = att + (size_t)(b * T_ + q0 + r0 + i) * E_ + h * DH_ + c0;
        float4 o;
        o.x = acc[i][0] * inv; o.y = acc[i][1] * inv;
        o.z = acc[i][2] * inv; o.w = acc[i][3] * inv;
        *(float4*)dst = o;
    }
}

// ---------------------------------------------------------------------------
// Launch: QKV GEMM -> flash attention -> projection GEMM
// ---------------------------------------------------------------------------
extern "C" void kernel_launch(void* const* d_in, const int* in_sizes, int n_in,
                              void* d_out, int out_size)
{
    (void)in_sizes; (void)n_in; (void)out_size;
    const float* x      = (const float*)d_in[0];
    const float* w_qkv  = (const float*)d_in[1];
    const float* b_qkv  = (const float*)d_in[2];
    const float* w_proj = (const float*)d_in[3];
    const float* b_proj = (const float*)d_in[4];
    float* out = (float*)d_out;

    float *qkv = nullptr, *attb = nullptr;
    cudaGetSymbolAddress((void**)&qkv,  g_qkv);
    cudaGetSymbolAddress((void**)&attb, g_att);

    cudaFuncSetAttribute(flash_attn,
                         cudaFuncAttributeMaxDynamicSharedMemorySize,
                         (int)FL_SMEM);

    // 1) qkv[M, 3E] = x[M, E] @ w_qkv[3E, E]^T + b_qkv
    sgemm_nt_bias<<<dim3(NQKV / 128, M_ / 128), 256>>>(
        x, w_qkv, b_qkv, qkv, M_, NQKV, E_);

    // 2) causal attention per (b, h)
    flash_attn<<<dim3(T_ / 64, B_ * H_), 256, FL_SMEM>>>(qkv, attb);

    // 3) out[M, E] = att[M, E] @ w_proj[E, E]^T + b_proj
    sgemm_nt_bias<<<dim3(E_ / 128, M_ / 128), 256>>>(
        attb, w_proj, b_proj, out, M_, E_, E_);
}

// round 4
// speedup vs baseline: 1.0564x; 1.0564x over previous
#include <cuda_runtime.h>

// Problem constants
#define B_   4
#define T_   2048
#define E_   1024
#define H_   16
#define DH_  64
#define M_   (B_ * T_)     // 8192 rows
#define NQKV (3 * E_)      // 3072

// Scratch (allocation-free rule: __device__ globals)
__device__ float g_qkv[(size_t)M_ * NQKV];  // 96 MB: [M, 3E]  (Q | K | V per row)
__device__ float g_att[(size_t)M_ * E_];    // 32 MB: attention output [M, E]

// ---------------------------------------------------------------------------
// NT SGEMM with bias: C[M,N] = A[M,K] @ B[N,K]^T + bias[N]
// 128x128 block tile, BK=8, 256 threads, 8x8 per-thread micro-tile split as
// 2x(4 rows)+2x(4 cols) at +64 offsets to minimize smem read conflicts.
// M,N,K assumed multiples of 128/128/8 (true for all calls here).
// ---------------------------------------------------------------------------
__global__ __launch_bounds__(256) void sgemm_nt_bias(
    const float* __restrict__ A, const float* __restrict__ Bm,
    const float* __restrict__ bias, float* __restrict__ C,
    int M, int N, int K)
{
    __shared__ float As[8][128];
    __shared__ float Bs[8][128];

    const int tid  = threadIdx.x;
    const int m0   = blockIdx.y * 128;
    const int n0   = blockIdx.x * 128;
    const int lrow = tid >> 1;           // 0..127
    const int lcol = (tid & 1) << 2;     // 0 or 4
    const int tx   = tid & 15;
    const int ty   = tid >> 4;

    const float* Ap = A  + (size_t)(m0 + lrow) * K + lcol;
    const float* Bp = Bm + (size_t)(n0 + lrow) * K + lcol;

    float acc[8][8];
    #pragma unroll
    for (int i = 0; i < 8; ++i)
        #pragma unroll
        for (int j = 0; j < 8; ++j) acc[i][j] = 0.f;

    for (int k0 = 0; k0 < K; k0 += 8) {
        float4 av = *(const float4*)(Ap + k0);
        float4 bv = *(const float4*)(Bp + k0);
        As[lcol + 0][lrow] = av.x; As[lcol + 1][lrow] = av.y;
        As[lcol + 2][lrow] = av.z; As[lcol + 3][lrow] = av.w;
        Bs[lcol + 0][lrow] = bv.x; Bs[lcol + 1][lrow] = bv.y;
        Bs[lcol + 2][lrow] = bv.z; Bs[lcol + 3][lrow] = bv.w;
        __syncthreads();

        #pragma unroll
        for (int k = 0; k < 8; ++k) {
            float a[8], b[8];
            float4 t0 = *(const float4*)&As[k][ty * 4];
            float4 t1 = *(const float4*)&As[k][ty * 4 + 64];
            a[0] = t0.x; a[1] = t0.y; a[2] = t0.z; a[3] = t0.w;
            a[4] = t1.x; a[5] = t1.y; a[6] = t1.z; a[7] = t1.w;
            float4 u0 = *(const float4*)&Bs[k][tx * 4];
            float4 u1 = *(const float4*)&Bs[k][tx * 4 + 64];
            b[0] = u0.x; b[1] = u0.y; b[2] = u0.z; b[3] = u0.w;
            b[4] = u1.x; b[5] = u1.y; b[6] = u1.z; b[7] = u1.w;
            #pragma unroll
            for (int i = 0; i < 8; ++i)
                #pragma unroll
                for (int j = 0; j < 8; ++j)
                    acc[i][j] += a[i] * b[j];
        }
        __syncthreads();
    }

    // Epilogue: rows m0 + ih*64 + ty*4 + i, cols n0 + jh*64 + tx*4 + j
    #pragma unroll
    for (int ih = 0; ih < 2; ++ih) {
        #pragma unroll
        for (int i = 0; i < 4; ++i) {
            const int row = m0 + ih * 64 + ty * 4 + i;
            #pragma unroll
            for (int jh = 0; jh < 2; ++jh) {
                const int col = n0 + jh * 64 + tx * 4;
                float4 o;
                o.x = acc[ih * 4 + i][jh * 4 + 0] + bias[col + 0];
                o.y = acc[ih * 4 + i][jh * 4 + 1] + bias[col + 1];
                o.z = acc[ih * 4 + i][jh * 4 + 2] + bias[col + 2];
                o.w = acc[ih * 4 + i][jh * 4 + 3] + bias[col + 3];
                *(float4*)(C + (size_t)row * N + col) = o;
            }
        }
    }
}

// ---------------------------------------------------------------------------
// Flash attention (fp32, causal). One block = 64 query rows of one (b,h).
// 256 threads: ty=tid/16 picks 4 query rows (r0=4*ty), tx=tid%16 picks 4 cols
// (c0=4*tx) — the same mapping serves the S tile (cols = keys) and the O tile
// (cols = head dims). Online softmax with per-row stats replicated across the
// 16 lanes of a row group (reduced with xor-shuffles within the low 4 lane
// bits, which never cross the ty boundary at bit 4).
// ---------------------------------------------------------------------------
#define FL_LDP 65                         // padded row stride (floats)
#define FL_SMEM (4 * 64 * FL_LDP * sizeof(float))   // Qs,Ks,Ps,Vs = 66560 B

__global__ __launch_bounds__(256) void flash_attn(
    const float* __restrict__ qkv, float* __restrict__ att)
{
    extern __shared__ float sm[];
    float* Qs = sm;
    float* Ks = sm + 1 * 64 * FL_LDP;
    float* Ps = sm + 2 * 64 * FL_LDP;
    float* Vs = sm + 3 * 64 * FL_LDP;

    const int tid = threadIdx.x;
    const int tx  = tid & 15;
    const int ty  = tid >> 4;
    const int r0  = ty * 4;
    const int c0  = tx * 4;
    const int q0  = blockIdx.x * 64;
    const int b   = blockIdx.y >> 4;
    const int h   = blockIdx.y & 15;

    const float* qb = qkv + (size_t)b * T_ * NQKV + h * DH_;
    const float* kb = qb + E_;
    const float* vb = qb + 2 * E_;

    // cooperative tile-load indexing: 4 threads per row, 16 floats each
    const int lr = tid >> 2;         // 0..63
    const int lc = (tid & 3) * 16;   // 0,16,32,48

    { // load Q tile once
        const float* src = qb + (size_t)(q0 + lr) * NQKV + lc;
        #pragma unroll
        for (int u = 0; u < 4; ++u) {
            float4 v = *(const float4*)(src + u * 4);
            float* d = Qs + lr * FL_LDP + lc + u * 4;
            d[0] = v.x; d[1] = v.y; d[2] = v.z; d[3] = v.w;
        }
    }

    float m[4], l[4], acc[4][4];
    #pragma unroll
    for (int i = 0; i < 4; ++i) {
        m[i] = -1e30f; l[i] = 0.f;
        #pragma unroll
        for (int j = 0; j < 4; ++j) acc[i][j] = 0.f;
    }

    for (int j0 = 0; j0 <= q0; j0 += 64) {
        __syncthreads();   // prev tile's P·V done reading Ps/Vs
        { // load K/V tiles
            const float* ksrc = kb + (size_t)(j0 + lr) * NQKV + lc;
            const float* vsrc = vb + (size_t)(j0 + lr) * NQKV + lc;
            #pragma unroll
            for (int u = 0; u < 4; ++u) {
                float4 kv4 = *(const float4*)(ksrc + u * 4);
                float4 vv4 = *(const float4*)(vsrc + u * 4);
                float* dk = Ks + lr * FL_LDP + lc + u * 4;
                float* dv = Vs + lr * FL_LDP + lc + u * 4;
                dk[0] = kv4.x; dk[1] = kv4.y; dk[2] = kv4.z; dk[3] = kv4.w;
                dv[0] = vv4.x; dv[1] = vv4.y; dv[2] = vv4.z; dv[3] = vv4.w;
            }
        }
        __syncthreads();

        // S = Q K^T (4x4 micro-tile, dot over 64)
        float s[4][4];
        #pragma unroll
        for (int i = 0; i < 4; ++i)
            #pragma unroll
            for (int j = 0; j < 4; ++j) s[i][j] = 0.f;

        #pragma unroll 8
        for (int k = 0; k < 64; ++k) {
            float qv[4], kv[4];
            #pragma unroll
            for (int i = 0; i < 4; ++i) qv[i] = Qs[(r0 + i) * FL_LDP + k];
            #pragma unroll
            for (int j = 0; j < 4; ++j) kv[j] = Ks[(c0 + j) * FL_LDP + k];
            #pragma unroll
            for (int i = 0; i < 4; ++i)
                #pragma unroll
                for (int j = 0; j < 4; ++j)
                    s[i][j] += qv[i] * kv[j];
        }

        const bool diag = (j0 == q0);
        #pragma unroll
        for (int i = 0; i < 4; ++i) {
            const int gr = q0 + r0 + i;
            float mx = -1e30f;
            #pragma unroll
            for (int j = 0; j < 4; ++j) {
                float sv = s[i][j] * 0.125f;   // SCALE = DH^-0.5 = 1/8 exactly
                if (diag && (j0 + c0 + j > gr)) sv = -1e30f;
                s[i][j] = sv;
                mx = fmaxf(mx, sv);
            }
            #pragma unroll
            for (int d = 8; d > 0; d >>= 1)
                mx = fmaxf(mx, __shfl_xor_sync(0xffffffffu, mx, d));
            const float mnew  = fmaxf(m[i], mx);
            const float alpha = __expf(m[i] - mnew);
            float rs = 0.f;
            #pragma unroll
            for (int j = 0; j < 4; ++j) {
                float p = __expf(s[i][j] - mnew);
                Ps[(r0 + i) * FL_LDP + c0 + j] = p;
                rs += p;
            }
            #pragma unroll
            for (int d = 8; d > 0; d >>= 1)
                rs += __shfl_xor_sync(0xffffffffu, rs, d);
            l[i] = l[i] * alpha + rs;
            m[i] = mnew;
            #pragma unroll
            for (int j = 0; j < 4; ++j) acc[i][j] *= alpha;
        }
        __syncthreads();   // Ps complete

        // O += P V (4 rows x 4 head-dims, sum over 64 keys)
        #pragma unroll 8
        for (int j = 0; j < 64; ++j) {
            float pv[4], vv[4];
            #pragma unroll
            for (int i = 0; i < 4; ++i) pv[i] = Ps[(r0 + i) * FL_LDP + j];
            #pragma unroll
            for (int d = 0; d < 4; ++d) vv[d] = Vs[j * FL_LDP + c0 + d];
            #pragma unroll
            for (int i = 0; i < 4; ++i)
                #pragma unroll
                for (int d = 0; d < 4; ++d)
                    acc[i][d] += pv[i] * vv[d];
        }
    }

    #pragma unroll
    for (int i = 0; i < 4; ++i) {
        const float inv = 1.0f / l[i];
        float* dst = att + (size_t)(b * T_ + q0 + r0 + i) * E_ + h * DH_ + c0;
        float4 o;
        o.x = acc[i][0] * inv; o.y = acc[i][1] * inv;
        o.z = acc[i][2] * inv; o.w = acc[i][3] * inv;
        *(float4*)dst = o;
    }
}

// ---------------------------------------------------------------------------
// Launch: QKV GEMM -> flash attention -> projection GEMM
// ---------------------------------------------------------------------------
extern "C" void kernel_launch(void* const* d_in, const int* in_sizes, int n_in,
                              void* d_out, int out_size)
{
    (void)in_sizes; (void)n_in; (void)out_size;
    const float* x      = (const float*)d_in[0];
    const float* w_qkv  = (const float*)d_in[1];
    const float* b_qkv  = (const float*)d_in[2];
    const float* w_proj = (const float*)d_in[3];
    const float* b_proj = (const float*)d_in[4];
    float* out = (float*)d_out;

    float *qkv = nullptr, *attb = nullptr;
    cudaGetSymbolAddress((void**)&qkv,  g_qkv);
    cudaGetSymbolAddress((void**)&attb, g_att);

    cudaFuncSetAttribute(flash_attn,
                         cudaFuncAttributeMaxDynamicSharedMemorySize,
                         (int)FL_SMEM);

    // 1) qkv[M, 3E] = x[M, E] @ w_qkv[3E, E]^T + b_qkv
    sgemm_nt_bias<<<dim3(NQKV / 128, M_ / 128), 256>>>(
        x, w_qkv, b_qkv, qkv, M_, NQKV, E_);

    // 2) causal attention per (b, h)
    flash_attn<<<dim3(T_ / 64, B_ * H_), 256, FL_SMEM>>>(qkv, attb);

    // 3) out[M, E] = att[M, E] @ w_proj[E, E]^T + b_proj
    sgemm_nt_bias<<<dim3(E_ / 128, M_ / 128), 256>>>(
        attb, w_proj, b_proj, out, M_, E_, E_);
}

// round 5
// speedup vs baseline: 1.0590x; 1.0025x over previous
#include <cuda_runtime.h>

// Problem constants
#define B_   4
#define T_   2048
#define E_   1024
#define H_   16
#define DH_  64
#define M_   (B_ * T_)     // 8192 rows
#define NQKV (3 * E_)      // 3072

// Scratch (allocation-free rule: __device__ globals)
__device__ float g_qkv[(size_t)M_ * NQKV];  // 96 MB: [M, 3E]  (Q | K | V per row)
__device__ float g_att[(size_t)M_ * E_];    // 32 MB: attention output [M, E]

// ---------------------------------------------------------------------------
// NT SGEMM with bias: C[M,N] = A[M,K] @ B[N,K]^T + bias[N]
// 128x128 block tile, BK=8, 256 threads, 8x8 per-thread micro-tile split as
// 2x(4 rows)+2x(4 cols) at +64 offsets to minimize smem read conflicts.
// M,N,K assumed multiples of 128/128/8 (true for all calls here).
// ---------------------------------------------------------------------------
__global__ __launch_bounds__(256) void sgemm_nt_bias(
    const float* __restrict__ A, const float* __restrict__ Bm,
    const float* __restrict__ bias, float* __restrict__ C,
    int M, int N, int K)
{
    __shared__ float As[8][128];
    __shared__ float Bs[8][128];

    const int tid  = threadIdx.x;
    const int m0   = blockIdx.y * 128;
    const int n0   = blockIdx.x * 128;
    const int lrow = tid >> 1;           // 0..127
    const int lcol = (tid & 1) << 2;     // 0 or 4
    const int tx   = tid & 15;
    const int ty   = tid >> 4;

    const float* Ap = A  + (size_t)(m0 + lrow) * K + lcol;
    const float* Bp = Bm + (size_t)(n0 + lrow) * K + lcol;

    float acc[8][8];
    #pragma unroll
    for (int i = 0; i < 8; ++i)
        #pragma unroll
        for (int j = 0; j < 8; ++j) acc[i][j] = 0.f;

    for (int k0 = 0; k0 < K; k0 += 8) {
        float4 av = *(const float4*)(Ap + k0);
        float4 bv = *(const float4*)(Bp + k0);
        As[lcol + 0][lrow] = av.x; As[lcol + 1][lrow] = av.y;
        As[lcol + 2][lrow] = av.z; As[lcol + 3][lrow] = av.w;
        Bs[lcol + 0][lrow] = bv.x; Bs[lcol + 1][lrow] = bv.y;
        Bs[lcol + 2][lrow] = bv.z; Bs[lcol + 3][lrow] = bv.w;
        __syncthreads();

        #pragma unroll
        for (int k = 0; k < 8; ++k) {
            float a[8], b[8];
            float4 t0 = *(const float4*)&As[k][ty * 4];
            float4 t1 = *(const float4*)&As[k][ty * 4 + 64];
            a[0] = t0.x; a[1] = t0.y; a[2] = t0.z; a[3] = t0.w;
            a[4] = t1.x; a[5] = t1.y; a[6] = t1.z; a[7] = t1.w;
            float4 u0 = *(const float4*)&Bs[k][tx * 4];
            float4 u1 = *(const float4*)&Bs[k][tx * 4 + 64];
            b[0] = u0.x; b[1] = u0.y; b[2] = u0.z; b[3] = u0.w;
            b[4] = u1.x; b[5] = u1.y; b[6] = u1.z; b[7] = u1.w;
            #pragma unroll
            for (int i = 0; i < 8; ++i)
                #pragma unroll
                for (int j = 0; j < 8; ++j)
                    acc[i][j] += a[i] * b[j];
        }
        __syncthreads();
    }

    // Epilogue: rows m0 + ih*64 + ty*4 + i, cols n0 + jh*64 + tx*4 + j
    #pragma unroll
    for (int ih = 0; ih < 2; ++ih) {
        #pragma unroll
        for (int i = 0; i < 4; ++i) {
            const int row = m0 + ih * 64 + ty * 4 + i;
            #pragma unroll
            for (int jh = 0; jh < 2; ++jh) {
                const int col = n0 + jh * 64 + tx * 4;
                float4 o;
                o.x = acc[ih * 4 + i][jh * 4 + 0] + bias[col + 0];
                o.y = acc[ih * 4 + i][jh * 4 + 1] + bias[col + 1];
                o.z = acc[ih * 4 + i][jh * 4 + 2] + bias[col + 2];
                o.w = acc[ih * 4 + i][jh * 4 + 3] + bias[col + 3];
                *(float4*)(C + (size_t)row * N + col) = o;
            }
        }
    }
}

// ---------------------------------------------------------------------------
// Flash attention (fp32, causal). One block = 64 query rows of one (b,h).
// 256 threads: ty=tid/16 picks 4 query rows (r0=4*ty), tx=tid%16 picks 4 cols
// (c0=4*tx) — the same mapping serves the S tile (cols = keys) and the O tile
// (cols = head dims). Online softmax with per-row stats replicated across the
// 16 lanes of a row group (reduced with xor-shuffles within the low 4 lane
// bits, which never cross the ty boundary at bit 4).
// ---------------------------------------------------------------------------
#define FL_LDP 65                         // padded row stride (floats)
#define FL_SMEM (4 * 64 * FL_LDP * sizeof(float))   // Qs,Ks,Ps,Vs = 66560 B

__global__ __launch_bounds__(256) void flash_attn(
    const float* __restrict__ qkv, float* __restrict__ att)
{
    extern __shared__ float sm[];
    float* Qs = sm;
    float* Ks = sm + 1 * 64 * FL_LDP;
    float* Ps = sm + 2 * 64 * FL_LDP;
    float* Vs = sm + 3 * 64 * FL_LDP;

    const int tid = threadIdx.x;
    const int tx  = tid & 15;
    const int ty  = tid >> 4;
    const int r0  = ty * 4;
    const int c0  = tx * 4;
    const int q0  = blockIdx.x * 64;
    const int b   = blockIdx.y >> 4;
    const int h   = blockIdx.y & 15;

    const float* qb = qkv + (size_t)b * T_ * NQKV + h * DH_;
    const float* kb = qb + E_;
    const float* vb = qb + 2 * E_;

    // cooperative tile-load indexing: 4 threads per row, 16 floats each
    const int lr = tid >> 2;         // 0..63
    const int lc = (tid & 3) * 16;   // 0,16,32,48

    { // load Q tile once
        const float* src = qb + (size_t)(q0 + lr) * NQKV + lc;
        #pragma unroll
        for (int u = 0; u < 4; ++u) {
            float4 v = *(const float4*)(src + u * 4);
            float* d = Qs + lr * FL_LDP + lc + u * 4;
            d[0] = v.x; d[1] = v.y; d[2] = v.z; d[3] = v.w;
        }
    }

    float m[4], l[4], acc[4][4];
    #pragma unroll
    for (int i = 0; i < 4; ++i) {
        m[i] = -1e30f; l[i] = 0.f;
        #pragma unroll
        for (int j = 0; j < 4; ++j) acc[i][j] = 0.f;
    }

    for (int j0 = 0; j0 <= q0; j0 += 64) {
        __syncthreads();   // prev tile's P·V done reading Ps/Vs
        { // load K/V tiles
            const float* ksrc = kb + (size_t)(j0 + lr) * NQKV + lc;
            const float* vsrc = vb + (size_t)(j0 + lr) * NQKV + lc;
            #pragma unroll
            for (int u = 0; u < 4; ++u) {
                float4 kv4 = *(const float4*)(ksrc + u * 4);
                float4 vv4 = *(const float4*)(vsrc + u * 4);
                float* dk = Ks + lr * FL_LDP + lc + u * 4;
                float* dv = Vs + lr * FL_LDP + lc + u * 4;
                dk[0] = kv4.x; dk[1] = kv4.y; dk[2] = kv4.z; dk[3] = kv4.w;
                dv[0] = vv4.x; dv[1] = vv4.y; dv[2] = vv4.z; dv[3] = vv4.w;
            }
        }
        __syncthreads();

        // S = Q K^T (4x4 micro-tile, dot over 64)
        float s[4][4];
        #pragma unroll
        for (int i = 0; i < 4; ++i)
            #pragma unroll
            for (int j = 0; j < 4; ++j) s[i][j] = 0.f;

        #pragma unroll 8
        for (int k = 0; k < 64; ++k) {
            float qv[4], kv[4];
            #pragma unroll
            for (int i = 0; i < 4; ++i) qv[i] = Qs[(r0 + i) * FL_LDP + k];
            #pragma unroll
            for (int j = 0; j < 4; ++j) kv[j] = Ks[(c0 + j) * FL_LDP + k];
            #pragma unroll
            for (int i = 0; i < 4; ++i)
                #pragma unroll
                for (int j = 0; j < 4; ++j)
                    s[i][j] += qv[i] * kv[j];
        }

        const bool diag = (j0 == q0);
        #pragma unroll
        for (int i = 0; i < 4; ++i) {
            const int gr = q0 + r0 + i;
            float mx = -1e30f;
            #pragma unroll
            for (int j = 0; j < 4; ++j) {
                float sv = s[i][j] * 0.125f;   // SCALE = DH^-0.5 = 1/8 exactly
                if (diag && (j0 + c0 + j > gr)) sv = -1e30f;
                s[i][j] = sv;
                mx = fmaxf(mx, sv);
            }
            #pragma unroll
            for (int d = 8; d > 0; d >>= 1)
                mx = fmaxf(mx, __shfl_xor_sync(0xffffffffu, mx, d));
            const float mnew  = fmaxf(m[i], mx);
            const float alpha = __expf(m[i] - mnew);
            float rs = 0.f;
            #pragma unroll
            for (int j = 0; j < 4; ++j) {
                float p = __expf(s[i][j] - mnew);
                Ps[(r0 + i) * FL_LDP + c0 + j] = p;
                rs += p;
            }
            #pragma unroll
            for (int d = 8; d > 0; d >>= 1)
                rs += __shfl_xor_sync(0xffffffffu, rs, d);
            l[i] = l[i] * alpha + rs;
            m[i] = mnew;
            #pragma unroll
            for (int j = 0; j < 4; ++j) acc[i][j] *= alpha;
        }
        __syncthreads();   // Ps complete

        // O += P V (4 rows x 4 head-dims, sum over 64 keys)
        #pragma unroll 8
        for (int j = 0; j < 64; ++j) {
            float pv[4], vv[4];
            #pragma unroll
            for (int i = 0; i < 4; ++i) pv[i] = Ps[(r0 + i) * FL_LDP + j];
            #pragma unroll
            for (int d = 0; d < 4; ++d) vv[d] = Vs[j * FL_LDP + c0 + d];
            #pragma unroll
            for (int i = 0; i < 4; ++i)
                #pragma unroll
                for (int d = 0; d < 4; ++d)
                    acc[i][d] += pv[i] * vv[d];
        }
    }

    #pragma unroll
    for (int i = 0; i < 4; ++i) {
        const float inv = 1.0f / l[i];
        float* dst = att + (size_t)(b * T_ + q0 + r0 + i) * E_ + h * DH_ + c0;
        float4 o;
        o.x = acc[i][0] * inv; o.y = acc[i][1] * inv;
        o.z = acc[i][2] * inv; o.w = acc[i][3] * inv;
        *(float4*)dst = o;
    }
}

// ---------------------------------------------------------------------------
// Launch: QKV GEMM -> flash attention -> projection GEMM
// ---------------------------------------------------------------------------
extern "C" void kernel_launch(void* const* d_in, const int* in_sizes, int n_in,
                              void* d_out, int out_size)
{
    (void)in_sizes; (void)n_in; (void)out_size;
    const float* x      = (const float*)d_in[0];
    const float* w_qkv  = (const float*)d_in[1];
    const float* b_qkv  = (const float*)d_in[2];
    const float* w_proj = (const float*)d_in[3];
    const float* b_proj = (const float*)d_in[4];
    float* out = (float*)d_out;

    float *qkv = nullptr, *attb = nullptr;
    cudaGetSymbolAddress((void**)&qkv,  g_qkv);
    cudaGetSymbolAddress((void**)&attb, g_att);

    cudaFuncSetAttribute(flash_attn,
                         cudaFuncAttributeMaxDynamicSharedMemorySize,
                         (int)FL_SMEM);

    // 1) qkv[M, 3E] = x[M, E] @ w_qkv[3E, E]^T + b_qkv
    sgemm_nt_bias<<<dim3(NQKV / 128, M_ / 128), 256>>>(
        x, w_qkv, b_qkv, qkv, M_, NQKV, E_);

    // 2) causal attention per (b, h)
    flash_attn<<<dim3(T_ / 64, B_ * H_), 256, FL_SMEM>>>(qkv, attb);

    // 3) out[M, E] = att[M, E] @ w_proj[E, E]^T + b_proj
    sgemm_nt_bias<<<dim3(E_ / 128, M_ / 128), 256>>>(
        attb, w_proj, b_proj, out, M_, E_, E_);
}